// round 2
// baseline (speedup 1.0000x reference)
#include <cuda_runtime.h>
#include <math.h>

// Problem dims
#define BATCH 32
#define TT    1024
#define DD    512
#define HH    512
#define GG    2048          // 4*H
#define LLAY  2
#define MM    (BATCH*TT)    // 32768

// Output layout in d_out (float32): seq [B,T,H], then h [B,L,H], then c [B,L,H]
#define SEQ_ELEMS  ((size_t)MM*HH)                 // 16777216
#define HOFF       (SEQ_ELEMS)
#define COFF       (SEQ_ELEMS + (size_t)BATCH*LLAY*HH)

// Recurrence kernel config
#define NBLK   128
#define NTHR   256
#define PADROW 516          // 512 + 4 pad floats to dodge bank conflicts
#define WS_ELEMS (16*PADROW)
#define HS_ELEMS (32*PADROW)
#define GSM_ELEMS (BATCH*16)
#define RSMEM_BYTES ((WS_ELEMS + HS_ELEMS + GSM_ELEMS) * sizeof(float))

// Scratch (device globals — no allocations allowed)
__device__ float g_xg[(size_t)MM*GG];     // 256 MB: precomputed input gates for current layer
__device__ float g_seq0[(size_t)MM*HH];   // 64 MB: layer-0 output sequence
__device__ float g_hbuf[2][BATCH*HH];     // double-buffered h
__device__ unsigned g_bar_count;
__device__ unsigned g_bar_gen;

// ---------------------------------------------------------------------------
// SGEMM: C[M,N] = A[M,K] @ W[K,N] + bias1[N] + bias2[N]
// 128x128 block tile, BK=8, 256 threads, 8x8 per thread. M,N multiples of 128;
// K multiple of 8 (all true here: M=32768, N=2048, K=512).
// ---------------------------------------------------------------------------
__global__ void __launch_bounds__(256, 2)
sgemm_bias(const float* __restrict__ A, const float* __restrict__ W,
           const float* __restrict__ bias1, const float* __restrict__ bias2,
           float* __restrict__ C, int Kdim)
{
    __shared__ float As[8][128];
    __shared__ float Bs[8][128];

    const int tid = threadIdx.x;
    const int brow = blockIdx.y, bcol = blockIdx.x;

    const float* Ablk = A + (size_t)brow * 128 * Kdim;
    const float* Wblk = W + (size_t)bcol * 128;

    const int arow = tid >> 1;            // 0..127
    const int ak4  = (tid & 1) * 4;       // 0 or 4
    const int wrow = tid >> 5;            // 0..7
    const int wn4  = (tid & 31) * 4;      // 0..124

    const int ty = tid >> 4;              // 0..15
    const int tx = tid & 15;              // 0..15

    float acc[8][8];
#pragma unroll
    for (int i = 0; i < 8; i++)
#pragma unroll
        for (int j = 0; j < 8; j++) acc[i][j] = 0.f;

    for (int k0 = 0; k0 < Kdim; k0 += 8) {
        float4 av = *(const float4*)(Ablk + (size_t)arow * Kdim + k0 + ak4);
        As[ak4 + 0][arow] = av.x;
        As[ak4 + 1][arow] = av.y;
        As[ak4 + 2][arow] = av.z;
        As[ak4 + 3][arow] = av.w;
        float4 wv = *(const float4*)(Wblk + (size_t)(k0 + wrow) * GG + wn4);
        *(float4*)(&Bs[wrow][wn4]) = wv;
        __syncthreads();

#pragma unroll
        for (int kk = 0; kk < 8; kk++) {
            float a[8], b[8];
            *(float4*)&a[0] = *(const float4*)&As[kk][ty * 8];
            *(float4*)&a[4] = *(const float4*)&As[kk][ty * 8 + 4];
            *(float4*)&b[0] = *(const float4*)&Bs[kk][tx * 8];
            *(float4*)&b[4] = *(const float4*)&Bs[kk][tx * 8 + 4];
#pragma unroll
            for (int i = 0; i < 8; i++)
#pragma unroll
                for (int j = 0; j < 8; j++)
                    acc[i][j] = fmaf(a[i], b[j], acc[i][j]);
        }
        __syncthreads();
    }

    const int row0 = brow * 128 + ty * 8;
    const int col0 = bcol * 128 + tx * 8;
    float bs[8];
#pragma unroll
    for (int j = 0; j < 8; j++) bs[j] = bias1[col0 + j] + bias2[col0 + j];

#pragma unroll
    for (int i = 0; i < 8; i++) {
        float4 v0 = make_float4(acc[i][0] + bs[0], acc[i][1] + bs[1],
                                acc[i][2] + bs[2], acc[i][3] + bs[3]);
        float4 v1 = make_float4(acc[i][4] + bs[4], acc[i][5] + bs[5],
                                acc[i][6] + bs[6], acc[i][7] + bs[7]);
        *(float4*)(C + (size_t)(row0 + i) * GG + col0)     = v0;
        *(float4*)(C + (size_t)(row0 + i) * GG + col0 + 4) = v1;
    }
}

// ---------------------------------------------------------------------------
// Grid barrier: safe because grid (128) <= #SMs, so all blocks are resident.
// Self-resetting; gen counter grows monotonically across launches/replays.
// ---------------------------------------------------------------------------
__device__ __forceinline__ void grid_barrier()
{
    __syncthreads();
    if (threadIdx.x == 0) {
        __threadfence();
        volatile unsigned* vgen = &g_bar_gen;
        unsigned gen = *vgen;
        unsigned arrived = atomicAdd(&g_bar_count, 1u);
        if (arrived == gridDim.x - 1) {
            g_bar_count = 0;
            __threadfence();
            atomicAdd(&g_bar_gen, 1u);
        } else {
            while (*vgen == gen) { }
            __threadfence();
        }
    }
    __syncthreads();
}

// ---------------------------------------------------------------------------
// Persistent LSTM recurrence for one layer.
// Block b owns 4 hidden units j in [4b, 4b+4) -> 16 gate columns
// {g*512 + 4b + jj : g in 0..3, jj in 0..3}. c stays in registers.
// Per step: stage h(t-1) (ld.cg) into smem, gates = xg[:,t,cols] + h @ Whslice,
// cell update, write h(t) (st.cg), grid barrier.
// ---------------------------------------------------------------------------
__global__ void __launch_bounds__(NTHR, 1)
lstm_recur(const float* __restrict__ Wh_l,
           const float* __restrict__ xg,
           float* __restrict__ seq_out,    // [B,T,H]
           float* __restrict__ hc_out,     // d_out base (for final h,c)
           int layer)
{
    extern __shared__ float smem[];
    float* ws  = smem;                   // [16][PADROW] transposed W slice: ws[c][k]
    float* hs  = ws + WS_ELEMS;          // [32][PADROW] staged h
    float* gsm = hs + HS_ELEMS;          // [32][16] gates

    const int tid = threadIdx.x;
    const int blk = blockIdx.x;

    // compute-phase mapping
    const int c_local = tid & 15;        // 0..15
    const int grp     = tid >> 4;        // 0..15
    const int gate    = c_local >> 2;
    const int jj      = c_local & 3;
    const int col     = gate * 512 + blk * 4 + jj;   // global gate column

    // update-phase mapping (tid < 128)
    const int ub  = tid >> 2;            // batch 0..31
    const int uj  = tid & 3;             // 0..3
    const int ujg = blk * 4 + uj;        // hidden unit index

    // Load W slice transposed into smem (one time): ws[c][k] = Wh_l[k*G + col(c)]
    for (int i = tid; i < 16 * 512; i += NTHR) {
        int c = i >> 9, k = i & 511;
        int g2 = c >> 2, j2 = c & 3;
        ws[c * PADROW + k] = Wh_l[(size_t)k * GG + g2 * 512 + blk * 4 + j2];
    }

    // Zero h buffer 0 (h(-1) = 0) cooperatively
    for (int i = blk * NTHR + tid; i < BATCH * HH; i += NBLK * NTHR)
        __stcg(&g_hbuf[0][i], 0.f);

    float creg = 0.f;

    grid_barrier();

    for (int t = 0; t < TT; t++) {
        // ---- stage h(t-1) into smem (bypass L1: written by other SMs) ----
        const float4* hsrc = (const float4*)(&g_hbuf[t & 1][0]);
        for (int i = tid; i < (BATCH * HH) / 4; i += NTHR) {
            float4 v = __ldcg(hsrc + i);
            int row = i >> 7;            // 128 float4 per row
            int c4  = i & 127;
            *(float4*)(hs + row * PADROW + c4 * 4) = v;
        }
        __syncthreads();

        // ---- gates: 2 dot products per thread (b=grp and b=grp+16, column col)
        const int b0 = grp, b1 = grp + 16;
        float acc0 = xg[((size_t)b0 * TT + t) * GG + col];
        float acc1 = xg[((size_t)b1 * TT + t) * GG + col];

        const float4* wp  = (const float4*)(ws + c_local * PADROW);
        const float4* h0p = (const float4*)(hs + b0 * PADROW);
        const float4* h1p = (const float4*)(hs + b1 * PADROW);

        float a0x = 0.f, a0y = 0.f, a1x = 0.f, a1y = 0.f;
#pragma unroll 8
        for (int k4 = 0; k4 < 128; k4++) {
            float4 w  = wp[k4];
            float4 ha = h0p[k4];
            float4 hb = h1p[k4];
            a0x = fmaf(ha.x, w.x, a0x); a0y = fmaf(ha.y, w.y, a0y);
            a0x = fmaf(ha.z, w.z, a0x); a0y = fmaf(ha.w, w.w, a0y);
            a1x = fmaf(hb.x, w.x, a1x); a1y = fmaf(hb.y, w.y, a1y);
            a1x = fmaf(hb.z, w.z, a1x); a1y = fmaf(hb.w, w.w, a1y);
        }
        acc0 += a0x + a0y;
        acc1 += a1x + a1y;

        gsm[b0 * 16 + c_local] = acc0;
        gsm[b1 * 16 + c_local] = acc1;
        __syncthreads();

        // ---- cell update for 128 (b, j) pairs owned by this block ----
        if (tid < 128) {
            float f  = gsm[ub * 16 + 0  + uj];
            float g  = gsm[ub * 16 + 4  + uj];
            float ii = gsm[ub * 16 + 8  + uj];
            float o  = gsm[ub * 16 + 12 + uj];
            f  = 1.f / (1.f + expf(-f));
            ii = 1.f / (1.f + expf(-ii));
            o  = 1.f / (1.f + expf(-o));
            g  = tanhf(g);
            creg = f * creg + ii * g;
            float hval = o * tanhf(creg);

            __stcg(&g_hbuf[(t + 1) & 1][ub * HH + ujg], hval);
            seq_out[((size_t)ub * TT + t) * HH + ujg] = hval;

            if (t == TT - 1) {
                hc_out[HOFF + (size_t)(ub * LLAY + layer) * HH + ujg] = hval;
                hc_out[COFF + (size_t)(ub * LLAY + layer) * HH + ujg] = creg;
            }
        }

        grid_barrier();   // h(t) visible to all before next step reads it
    }
}

// ---------------------------------------------------------------------------
extern "C" void kernel_launch(void* const* d_in, const int* in_sizes, int n_in,
                              void* d_out, int out_size)
{
    const float* x  = (const float*)d_in[0];   // [B,T,D]
    const float* Wx = (const float*)d_in[1];   // [L,D,4H]
    const float* bx = (const float*)d_in[2];   // [L,4H]
    const float* Wh = (const float*)d_in[3];   // [L,H,4H]
    const float* bh = (const float*)d_in[4];   // [L,4H]
    float* out = (float*)d_out;

    float *xg = nullptr, *seq0 = nullptr;
    cudaGetSymbolAddress((void**)&xg, g_xg);
    cudaGetSymbolAddress((void**)&seq0, g_seq0);

    cudaFuncSetAttribute(lstm_recur, cudaFuncAttributeMaxDynamicSharedMemorySize,
                         (int)RSMEM_BYTES);

    dim3 gdim(GG / 128, MM / 128);

    // Layer 0
    sgemm_bias<<<gdim, 256>>>(x, Wx, bx, bh, xg, DD);
    lstm_recur<<<NBLK, NTHR, RSMEM_BYTES>>>(Wh, xg, seq0, out, 0);

    // Layer 1
    sgemm_bias<<<gdim, 256>>>(seq0, Wx + (size_t)DD * GG, bx + GG, bh + GG, xg, HH);
    lstm_recur<<<NBLK, NTHR, RSMEM_BYTES>>>(Wh + (size_t)HH * GG, xg, out, out, 1);
}